// round 14
// baseline (speedup 1.0000x reference)
#include <cuda_runtime.h>
#include <cstdint>
#include <math.h>

// NaiveFourierKANLayer, fp16 mma.sync single term, R14:
//  - CTA tile 128x256, 8 warps, 64x64 warp tiles
//  - fragment software pipelining: 2-slot A rotation + double-buffered B frags,
//    every LDSM issues under the previous 8-MMA run
//  - produce(it+1) interleaved inside consume(it) (R13)
//  - B pre-converted fp16 (x2048), cp.async fill; split-K 16; float4 reduce

#define NI 256
#define NG 300
#define NO 256
#define SPLITK 16
#define IPC (NI/SPLITK)      // 16 i per CTA
#define NGC 10               // 32-g chunks per i (chunk 9 zero-padded)
#define NSTAGE (IPC*NGC)     // 160

#define RSB 144
#define A_OFF 0
#define B_OFF 18432
#define STAGE_BYTES 55296
#define DYN_SMEM (2*STAGE_BYTES)

#define BSCALE 2048.0f
#define FSCALE (1.0f/2048.0f)

__device__ float    g_scratch[SPLITK * 1024 * 256];     // 16 MB
__device__ uint32_t g_Bh[256u * 256u * 10u * 32u];      // 83.9 MB fp16 B, smem-row layout

// ---------------- helpers ----------------
__device__ __forceinline__ uint32_t smem_u32(const void* p) {
    uint32_t a;
    asm("{ .reg .u64 t; cvta.to.shared.u64 t, %1; cvt.u32.u64 %0, t; }" : "=r"(a) : "l"(p));
    return a;
}
__device__ __forceinline__ uint32_t packf16(float a, float b) {
    uint32_t r;
    asm("cvt.rn.f16x2.f32 %0, %2, %1;" : "=r"(r) : "f"(a), "f"(b));
    return r;
}
__device__ __forceinline__ void rotstep(float& c, float& s, float cr, float sr) {
    float nc = fmaf(c, cr, -(s * sr));
    float ns = fmaf(s, cr, c * sr);
    c = nc; s = ns;
}

#define LDSM4(r0,r1,r2,r3,addr)                                                  \
    asm volatile("ldmatrix.sync.aligned.m8n8.x4.shared.b16 {%0,%1,%2,%3}, [%4];" \
        : "=r"(r0), "=r"(r1), "=r"(r2), "=r"(r3) : "r"(addr))

#define MMA(d,a,b0,b1)                                                        \
    asm volatile("mma.sync.aligned.m16n8k16.row.col.f32.f16.f16.f32 "         \
        "{%0,%1,%2,%3},{%4,%5,%6,%7},{%8,%9},{%0,%1,%2,%3};"                  \
        : "+f"((d)[0]), "+f"((d)[1]), "+f"((d)[2]), "+f"((d)[3])              \
        : "r"((a)[0]), "r"((a)[1]), "r"((a)[2]), "r"((a)[3]), "r"(b0), "r"(b1))

#define CP16(dst,src) \
    asm volatile("cp.async.cg.shared.global [%0], [%1], 16;" :: "r"(dst), "l"(src))
#define CP_COMMIT() asm volatile("cp.async.commit_group;" ::: "memory")
#define CP_WAIT0()  asm volatile("cp.async.wait_group 0;" ::: "memory")

extern __shared__ char dsmem[];

// ---------------- B pre-conversion (4 u32 / thread) ----------------
__global__ void __launch_bounds__(512, 2)
fkan_conv(const float* __restrict__ fc)
{
    const int idx = blockIdx.x * 512 + threadIdx.x;     // 5,242,880 threads
    const int u4  = idx & 7;
    const int t   = idx >> 3;
    const int gc  = t % NGC;
    const int i   = (t / NGC) & 255;
    const int j   = t / (NGC * 256);

    const int bt = u4 >> 2;                             // 0=W0/cos slot, 1=W1/sin slot
    const int g0 = gc * 32 + (u4 & 3) * 8;
    const float* src = fc + ((size_t)(bt * NO + j) * NI + i) * NG + g0;

    float4 f0 = (g0 + 3 < NG) ? *(const float4*)(src)
                              : make_float4(0.f, 0.f, 0.f, 0.f);
    float4 f1 = (g0 + 7 < NG) ? *(const float4*)(src + 4)
                              : make_float4(0.f, 0.f, 0.f, 0.f);
    uint4 o;
    o.x = packf16(f0.x * BSCALE, f0.y * BSCALE);
    o.y = packf16(f0.z * BSCALE, f0.w * BSCALE);
    o.z = packf16(f1.x * BSCALE, f1.y * BSCALE);
    o.w = packf16(f1.z * BSCALE, f1.w * BSCALE);
    *(uint4*)(g_Bh + (size_t)idx * 4) = o;
}

// ---------------- main MMA kernel ----------------
__global__ void __launch_bounds__(256, 1)
fkan_hmma(const float* __restrict__ x)
{
    const int tid  = threadIdx.x;
    const int lane = tid & 31;
    const int w    = tid >> 5;
    const int ks = blockIdx.x;
    const int m0 = blockIdx.y * 128;

    const uint32_t smb = smem_u32(dsmem);

    // producer maps
    const int rr = tid >> 1, q = tid & 1;               // A: row, g-half of 16
    const uint32_t* bsrc = g_Bh + (((uint32_t)tid * 256u + (uint32_t)(ks * IPC)) * 10u) * 32u;
    const uint32_t  bdst = (uint32_t)B_OFF + (uint32_t)tid * RSB;

    // mma maps: 8 warps = 2(M) x 4(N), warp tile 64x64
    const int wm = w & 1, wn = w >> 1;
    const uint32_t aoff = (uint32_t)(wm*64 + (lane & 7) + ((lane >> 3) & 1)*8) * RSB
                        + (uint32_t)(lane >> 4) * 16;
    const uint32_t boff = (uint32_t)(wn*64 + (lane & 7) + (lane >> 4)*8) * RSB
                        + (uint32_t)((lane >> 3) & 1) * 16;

    float acc[4][8][4];
    #pragma unroll
    for (int a = 0; a < 4; ++a)
        #pragma unroll
        for (int b = 0; b < 8; ++b)
            #pragma unroll
            for (int c = 0; c < 4; ++c) acc[a][b][c] = 0.f;

    const float* xcol = x + (size_t)(m0 + rr) * NI + ks * IPC;

    // rotation / production state (for NEXT stage)
    float c1, s1, c2, s2, c16, s16, cc, ss;
    int png = 0, pni = 0;

    #define SETUP_I(ii) do {                                                   \
        const float t_ = xcol[ii];                                             \
        sincosf(t_, &s1, &c1);                                                 \
        c2 = fmaf(c1, c1, -(s1*s1)); s2 = 2.f*c1*s1;                           \
        const float c4_ = fmaf(c2, c2, -(s2*s2)), s4_ = 2.f*c2*s2;             \
        const float c8_ = fmaf(c4_, c4_, -(s4_*s4_)), s8_ = 2.f*c4_*s4_;       \
        c16 = fmaf(c8_, c8_, -(s8_*s8_)); s16 = 2.f*c8_*s8_;                   \
        cc = c1; ss = s1;                                                      \
        if (q) rotstep(cc, ss, c16, s16);                                      \
    } while (0)

    #define GEN_PAIR(smn, m) do {                                              \
        const int gl_ = q*16 + 2*(m);                                          \
        const int gg_ = png*32 + gl_;                                          \
        float ce_ = cc, se_ = ss;                                              \
        float co_ = fmaf(cc, c1, -(ss*s1));                                    \
        float so_ = fmaf(ss, c1,  cc*s1);                                      \
        if (gg_     >= NG) { ce_ = 0.f; se_ = 0.f; }                           \
        if (gg_ + 1 >= NG) { co_ = 0.f; so_ = 0.f; }                           \
        const uint32_t offc_ = (uint32_t)rr * RSB + (uint32_t)gl_ * 2;         \
        *(uint32_t*)((smn) + A_OFF + offc_)      = packf16(ce_, co_);          \
        *(uint32_t*)((smn) + A_OFF + offc_ + 64) = packf16(se_, so_);          \
        rotstep(cc, ss, c2, s2);                                               \
    } while (0)

    #define END_CHUNK() do {                                                   \
        rotstep(cc, ss, c16, s16);                                             \
        if (++png == NGC) { png = 0; ++pni; }                                  \
    } while (0)

    // fragment slots
    uint32_t a0[4], a1[4], bh0[16], bh1[16];

    #define LDSM_B(dst, kkv) do {                                              \
        _Pragma("unroll")                                                      \
        for (int p = 0; p < 4; ++p)                                            \
            LDSM4((dst)[4*p], (dst)[4*p+1], (dst)[4*p+2], (dst)[4*p+3],        \
                  pB + p*(16*RSB) + (kkv)*32);                                 \
    } while (0)
    #define LDSM_A(dst, mfv, kkv)                                              \
        LDSM4((dst)[0], (dst)[1], (dst)[2], (dst)[3],                          \
              pA + (mfv)*(16*RSB) + (kkv)*32)
    #define MMA8(mfv, ahs, bhs) do {                                           \
        _Pragma("unroll")                                                      \
        for (int f = 0; f < 8; ++f)                                            \
            MMA(acc[mfv][f], ahs, (bhs)[2*f], (bhs)[2*f+1]);                   \
    } while (0)

    // kk block with slot rotation; optionally preload next kk's B + A(mf0)
    #define KKB(kkv, bhc, bhn, kkn, LB) do {                                   \
        LDSM_A(a1, 1, kkv); MMA8(0, a0, bhc);                                  \
        LDSM_A(a0, 2, kkv); MMA8(1, a1, bhc);                                  \
        LDSM_A(a1, 3, kkv); MMA8(2, a0, bhc);                                  \
        if (LB) { LDSM_B(bhn, kkn); LDSM_A(a0, 0, kkn); }                      \
        MMA8(3, a1, bhc);                                                      \
    } while (0)

    // ---- prologue: produce stage 0, issue cp(0) ----
    SETUP_I(0);
    {
        char* sm0 = dsmem;
        #pragma unroll
        for (int m = 0; m < 8; ++m) GEN_PAIR(sm0, m);
        END_CHUNK();
        const uint32_t d0 = smb + bdst;
        #pragma unroll
        for (int c = 0; c < 8; ++c) CP16(d0 + c * 16, bsrc + c * 4);
        CP_COMMIT();
    }

    int cgc = 0;
    for (int it = 0; it < NSTAGE; ++it) {
        CP_WAIT0();
        __syncthreads();                    // stage it fully visible

        const bool dp = (it + 1 < NSTAGE);
        char* smn = dsmem + ((it + 1) & 1) * STAGE_BYTES;

        // issue B cp.async for stage it+1
        if (dp) {
            const uint32_t* src = bsrc + (uint32_t)(it + 1) * 32u;
            const uint32_t d0 = smb + (uint32_t)(((it + 1) & 1) * STAGE_BYTES) + bdst;
            #pragma unroll
            for (int c = 0; c < 8; ++c) CP16(d0 + c * 16, src + c * 4);
            CP_COMMIT();
        }

        const uint32_t stg = (uint32_t)(it & 1) * STAGE_BYTES;
        const uint32_t pA = smb + stg + aoff;
        const uint32_t pB = smb + stg + B_OFF + boff;

        if (cgc != 9) {
            LDSM_B(bh0, 0); LDSM_A(a0, 0, 0);
            KKB(0, bh0, bh1, 1, true);
            if (dp) { if (png == 0) SETUP_I(pni); GEN_PAIR(smn, 0); GEN_PAIR(smn, 1); }
            KKB(1, bh1, bh0, 2, true);
            if (dp) { GEN_PAIR(smn, 2); GEN_PAIR(smn, 3); }
            KKB(2, bh0, bh1, 3, true);
            if (dp) { GEN_PAIR(smn, 4); GEN_PAIR(smn, 5); }
            KKB(3, bh1, bh0, 0, false);
            if (dp) { GEN_PAIR(smn, 6); GEN_PAIR(smn, 7); END_CHUNK(); }
        } else {
            // padded chunk: only kk=0 and kk=2 carry data
            LDSM_B(bh0, 0); LDSM_A(a0, 0, 0);
            KKB(0, bh0, bh1, 2, true);
            if (dp) {
                if (png == 0) SETUP_I(pni);
                GEN_PAIR(smn, 0); GEN_PAIR(smn, 1);
                GEN_PAIR(smn, 2); GEN_PAIR(smn, 3);
            }
            KKB(2, bh1, bh0, 0, false);
            if (dp) {
                GEN_PAIR(smn, 4); GEN_PAIR(smn, 5);
                GEN_PAIR(smn, 6); GEN_PAIR(smn, 7);
                END_CHUNK();
            }
        }
        if (++cgc == NGC) cgc = 0;
    }

    // ---- epilogue: accumulators (x2048) -> split-K scratch ----
    float* dst = g_scratch + ((size_t)ks << 18);
    #pragma unroll
    for (int mf = 0; mf < 4; ++mf) {
        const int r = m0 + wm*64 + mf*16 + (lane >> 2);
        #pragma unroll
        for (int f = 0; f < 8; ++f) {
            const int c = wn*64 + f*8 + (lane & 3)*2;
            float2 v0, v1;
            v0.x = acc[mf][f][0] * FSCALE; v0.y = acc[mf][f][1] * FSCALE;
            v1.x = acc[mf][f][2] * FSCALE; v1.y = acc[mf][f][3] * FSCALE;
            *(float2*)(dst + (size_t)r * NO + c)       = v0;
            *(float2*)(dst + (size_t)(r + 8) * NO + c) = v1;
        }
    }
}

// ---------------- split-K reduce (float4 per thread) ----------------
__global__ void __launch_bounds__(512, 1)
fkan_reduce(const float* __restrict__ bias, float* __restrict__ out)
{
    const int base = (blockIdx.x * 512 + threadIdx.x) * 4;   // 128 blocks -> 262144
    float4 a = *(const float4*)(bias + (base & 255));
    #pragma unroll
    for (int k = 0; k < SPLITK; ++k) {
        const float4 v = *(const float4*)(g_scratch + ((size_t)k << 18) + base);
        a.x += v.x; a.y += v.y; a.z += v.z; a.w += v.w;
    }
    *(float4*)(out + base) = a;
}

extern "C" void kernel_launch(void* const* d_in, const int* in_sizes, int n_in,
                              void* d_out, int out_size) {
    const float* x    = (const float*)d_in[0];
    const float* fc   = (const float*)d_in[1];
    const float* bias = (const float*)d_in[2];
    float* out        = (float*)d_out;

    cudaFuncSetAttribute(fkan_hmma, cudaFuncAttributeMaxDynamicSharedMemorySize, DYN_SMEM);
    fkan_conv<<<10240, 512>>>(fc);
    fkan_hmma<<<dim3(SPLITK, 8), 256, DYN_SMEM>>>(x);
    fkan_reduce<<<128, 512>>>(bias, out);
}

// round 15
// speedup vs baseline: 1.0770x; 1.0770x over previous
#include <cuda_runtime.h>
#include <cstdint>
#include <math.h>

// NaiveFourierKANLayer, fp16 mma.sync single term, R15:
//  - main = R13 structure (best measured: 357us, ~16.6 cyc/HMMA)
//  - uneven split-K 18 (grid 144 CTAs -> 97% SM fill; max 150 stages vs 160)
//  - float4 reduce; B pre-converted fp16 (x2048) via vectorized conv

#define NI 256
#define NG 300
#define NO 256
#define SPLITK 18
#define NGC 10               // 32-g chunks per i (chunk 9 zero-padded)

#define RSB 144
#define A_OFF 0
#define B_OFF 18432
#define STAGE_BYTES 55296
#define DYN_SMEM (2*STAGE_BYTES)

#define BSCALE 2048.0f
#define FSCALE (1.0f/2048.0f)

__device__ float    g_scratch[SPLITK * 1024 * 256];     // 18.9 MB
__device__ uint32_t g_Bh[256u * 256u * 10u * 32u];      // 83.9 MB fp16 B, smem-row layout

// ---------------- helpers ----------------
__device__ __forceinline__ uint32_t smem_u32(const void* p) {
    uint32_t a;
    asm("{ .reg .u64 t; cvta.to.shared.u64 t, %1; cvt.u32.u64 %0, t; }" : "=r"(a) : "l"(p));
    return a;
}
__device__ __forceinline__ uint32_t packf16(float a, float b) {
    uint32_t r;
    asm("cvt.rn.f16x2.f32 %0, %2, %1;" : "=r"(r) : "f"(a), "f"(b));
    return r;
}
__device__ __forceinline__ void rotstep(float& c, float& s, float cr, float sr) {
    float nc = fmaf(c, cr, -(s * sr));
    float ns = fmaf(s, cr, c * sr);
    c = nc; s = ns;
}

#define LDSM4(r0,r1,r2,r3,addr)                                                  \
    asm volatile("ldmatrix.sync.aligned.m8n8.x4.shared.b16 {%0,%1,%2,%3}, [%4];" \
        : "=r"(r0), "=r"(r1), "=r"(r2), "=r"(r3) : "r"(addr))

#define MMA(d,a,b0,b1)                                                        \
    asm volatile("mma.sync.aligned.m16n8k16.row.col.f32.f16.f16.f32 "         \
        "{%0,%1,%2,%3},{%4,%5,%6,%7},{%8,%9},{%0,%1,%2,%3};"                  \
        : "+f"((d)[0]), "+f"((d)[1]), "+f"((d)[2]), "+f"((d)[3])              \
        : "r"((a)[0]), "r"((a)[1]), "r"((a)[2]), "r"((a)[3]), "r"(b0), "r"(b1))

#define CP16(dst,src) \
    asm volatile("cp.async.cg.shared.global [%0], [%1], 16;" :: "r"(dst), "l"(src))
#define CP_COMMIT() asm volatile("cp.async.commit_group;" ::: "memory")
#define CP_WAIT0()  asm volatile("cp.async.wait_group 0;" ::: "memory")

extern __shared__ char dsmem[];

// ---------------- B pre-conversion (4 u32 / thread) ----------------
__global__ void __launch_bounds__(512, 2)
fkan_conv(const float* __restrict__ fc)
{
    const int idx = blockIdx.x * 512 + threadIdx.x;     // 5,242,880 threads
    const int u4  = idx & 7;
    const int t   = idx >> 3;
    const int gc  = t % NGC;
    const int i   = (t / NGC) & 255;
    const int j   = t / (NGC * 256);

    const int bt = u4 >> 2;                             // 0=W0/cos slot, 1=W1/sin slot
    const int g0 = gc * 32 + (u4 & 3) * 8;
    const float* src = fc + ((size_t)(bt * NO + j) * NI + i) * NG + g0;

    float4 f0 = (g0 + 3 < NG) ? *(const float4*)(src)
                              : make_float4(0.f, 0.f, 0.f, 0.f);
    float4 f1 = (g0 + 7 < NG) ? *(const float4*)(src + 4)
                              : make_float4(0.f, 0.f, 0.f, 0.f);
    uint4 o;
    o.x = packf16(f0.x * BSCALE, f0.y * BSCALE);
    o.y = packf16(f0.z * BSCALE, f0.w * BSCALE);
    o.z = packf16(f1.x * BSCALE, f1.y * BSCALE);
    o.w = packf16(f1.z * BSCALE, f1.w * BSCALE);
    *(uint4*)(g_Bh + (size_t)idx * 4) = o;
}

// ---------------- main MMA kernel ----------------
__global__ void __launch_bounds__(256, 1)
fkan_hmma(const float* __restrict__ x)
{
    const int tid  = threadIdx.x;
    const int lane = tid & 31;
    const int w    = tid >> 5;
    const int ks = blockIdx.x;                 // 0..17, uneven split-K over i
    const int m0 = blockIdx.y * 128;

    // slice boundaries: first 4 slices take 15 i, rest take 14 (4*15+14*14=256)
    const int i0  = ks * 14 + min(ks, 4);
    const int ipc = 14 + (ks < 4 ? 1 : 0);
    const int nst = ipc * NGC;

    const uint32_t smb = smem_u32(dsmem);

    // producer maps
    const int rr = tid >> 1, q = tid & 1;               // A: row, g-half of 16
    const uint32_t* bsrc = g_Bh + (((uint32_t)tid * 256u + (uint32_t)i0) * 10u) * 32u;
    const uint32_t  bdst = (uint32_t)B_OFF + (uint32_t)tid * RSB;

    // mma maps: 8 warps = 2(M) x 4(N), warp tile 64x64
    const int wm = w & 1, wn = w >> 1;
    const uint32_t aoff = (uint32_t)(wm*64 + (lane & 7) + ((lane >> 3) & 1)*8) * RSB
                        + (uint32_t)(lane >> 4) * 16;
    const uint32_t boff = (uint32_t)(wn*64 + (lane & 7) + (lane >> 4)*8) * RSB
                        + (uint32_t)((lane >> 3) & 1) * 16;

    float acc[4][8][4];
    #pragma unroll
    for (int a = 0; a < 4; ++a)
        #pragma unroll
        for (int b = 0; b < 8; ++b)
            #pragma unroll
            for (int c = 0; c < 4; ++c) acc[a][b][c] = 0.f;

    const float* xcol = x + (size_t)(m0 + rr) * NI + i0;

    // rotation / production state (for NEXT stage)
    float c1, s1, c2, s2, c16, s16, cc, ss;
    int png = 0, pni = 0;

    #define SETUP_I(ii) do {                                                   \
        const float t_ = xcol[ii];                                             \
        sincosf(t_, &s1, &c1);                                                 \
        c2 = fmaf(c1, c1, -(s1*s1)); s2 = 2.f*c1*s1;                           \
        const float c4_ = fmaf(c2, c2, -(s2*s2)), s4_ = 2.f*c2*s2;             \
        const float c8_ = fmaf(c4_, c4_, -(s4_*s4_)), s8_ = 2.f*c4_*s4_;       \
        c16 = fmaf(c8_, c8_, -(s8_*s8_)); s16 = 2.f*c8_*s8_;                   \
        cc = c1; ss = s1;                                                      \
        if (q) rotstep(cc, ss, c16, s16);                                      \
    } while (0)

    #define GEN_PAIR(smn, m) do {                                              \
        const int gl_ = q*16 + 2*(m);                                          \
        const int gg_ = png*32 + gl_;                                          \
        float ce_ = cc, se_ = ss;                                              \
        float co_ = fmaf(cc, c1, -(ss*s1));                                    \
        float so_ = fmaf(ss, c1,  cc*s1);                                      \
        if (gg_     >= NG) { ce_ = 0.f; se_ = 0.f; }                           \
        if (gg_ + 1 >= NG) { co_ = 0.f; so_ = 0.f; }                           \
        const uint32_t offc_ = (uint32_t)rr * RSB + (uint32_t)gl_ * 2;         \
        *(uint32_t*)((smn) + A_OFF + offc_)      = packf16(ce_, co_);          \
        *(uint32_t*)((smn) + A_OFF + offc_ + 64) = packf16(se_, so_);          \
        rotstep(cc, ss, c2, s2);                                               \
    } while (0)

    #define END_CHUNK() do {                                                   \
        rotstep(cc, ss, c16, s16);                                             \
        if (++png == NGC) { png = 0; ++pni; }                                  \
    } while (0)

    #define CONSUME_KK(kk) do {                                                \
        uint32_t bh[16];                                                       \
        _Pragma("unroll")                                                      \
        for (int p = 0; p < 4; ++p)                                            \
            LDSM4(bh[4*p], bh[4*p+1], bh[4*p+2], bh[4*p+3],                    \
                  pB + p*(16*RSB) + (kk)*32);                                  \
        uint32_t ah[4][4];                                                     \
        _Pragma("unroll")                                                      \
        for (int mf = 0; mf < 4; ++mf)                                         \
            LDSM4(ah[mf][0], ah[mf][1], ah[mf][2], ah[mf][3],                  \
                  pA + mf*(16*RSB) + (kk)*32);                                 \
        _Pragma("unroll")                                                      \
        for (int mf = 0; mf < 4; ++mf)                                         \
            _Pragma("unroll")                                                  \
            for (int f = 0; f < 8; ++f)                                        \
                MMA(acc[mf][f], ah[mf], bh[2*f], bh[2*f+1]);                   \
    } while (0)

    // ---- prologue: produce stage 0, issue cp(0) ----
    SETUP_I(0);
    {
        char* sm0 = dsmem;
        #pragma unroll
        for (int m = 0; m < 8; ++m) GEN_PAIR(sm0, m);
        END_CHUNK();
        const uint32_t d0 = smb + bdst;
        #pragma unroll
        for (int c = 0; c < 8; ++c) CP16(d0 + c * 16, bsrc + c * 4);
        CP_COMMIT();
    }

    int cgc = 0;
    for (int it = 0; it < nst; ++it) {
        CP_WAIT0();
        __syncthreads();                    // stage it fully visible

        const bool dp = (it + 1 < nst);
        char* smn = dsmem + ((it + 1) & 1) * STAGE_BYTES;

        // issue B cp.async for stage it+1
        if (dp) {
            const uint32_t* src = bsrc + (uint32_t)(it + 1) * 32u;
            const uint32_t d0 = smb + (uint32_t)(((it + 1) & 1) * STAGE_BYTES) + bdst;
            #pragma unroll
            for (int c = 0; c < 8; ++c) CP16(d0 + c * 16, src + c * 4);
            CP_COMMIT();
        }

        const uint32_t stg = (uint32_t)(it & 1) * STAGE_BYTES;
        const uint32_t pA = smb + stg + aoff;
        const uint32_t pB = smb + stg + B_OFF + boff;

        if (cgc != 9) {
            CONSUME_KK(0);
            if (dp) { if (png == 0) SETUP_I(pni); GEN_PAIR(smn, 0); GEN_PAIR(smn, 1); }
            CONSUME_KK(1);
            if (dp) { GEN_PAIR(smn, 2); GEN_PAIR(smn, 3); }
            CONSUME_KK(2);
            if (dp) { GEN_PAIR(smn, 4); GEN_PAIR(smn, 5); }
            CONSUME_KK(3);
            if (dp) { GEN_PAIR(smn, 6); GEN_PAIR(smn, 7); END_CHUNK(); }
        } else {
            // padded chunk: only kk=0 and kk=2 carry data
            CONSUME_KK(0);
            if (dp) {
                if (png == 0) SETUP_I(pni);
                GEN_PAIR(smn, 0); GEN_PAIR(smn, 1);
                GEN_PAIR(smn, 2); GEN_PAIR(smn, 3);
            }
            CONSUME_KK(2);
            if (dp) {
                GEN_PAIR(smn, 4); GEN_PAIR(smn, 5);
                GEN_PAIR(smn, 6); GEN_PAIR(smn, 7);
                END_CHUNK();
            }
        }
        if (++cgc == NGC) cgc = 0;
    }

    // ---- epilogue: accumulators (x2048) -> split-K scratch ----
    float* dst = g_scratch + ((size_t)ks << 18);
    #pragma unroll
    for (int mf = 0; mf < 4; ++mf) {
        const int r = m0 + wm*64 + mf*16 + (lane >> 2);
        #pragma unroll
        for (int f = 0; f < 8; ++f) {
            const int c = wn*64 + f*8 + (lane & 3)*2;
            float2 v0, v1;
            v0.x = acc[mf][f][0] * FSCALE; v0.y = acc[mf][f][1] * FSCALE;
            v1.x = acc[mf][f][2] * FSCALE; v1.y = acc[mf][f][3] * FSCALE;
            *(float2*)(dst + (size_t)r * NO + c)       = v0;
            *(float2*)(dst + (size_t)(r + 8) * NO + c) = v1;
        }
    }
}

// ---------------- split-K reduce (float4 per thread) ----------------
__global__ void __launch_bounds__(512, 1)
fkan_reduce(const float* __restrict__ bias, float* __restrict__ out)
{
    const int base = (blockIdx.x * 512 + threadIdx.x) * 4;   // 128 blocks -> 262144
    float4 a = *(const float4*)(bias + (base & 255));
    #pragma unroll
    for (int k = 0; k < SPLITK; ++k) {
        const float4 v = *(const float4*)(g_scratch + ((size_t)k << 18) + base);
        a.x += v.x; a.y += v.y; a.z += v.z; a.w += v.w;
    }
    *(float4*)(out + base) = a;
}

extern "C" void kernel_launch(void* const* d_in, const int* in_sizes, int n_in,
                              void* d_out, int out_size) {
    const float* x    = (const float*)d_in[0];
    const float* fc   = (const float*)d_in[1];
    const float* bias = (const float*)d_in[2];
    float* out        = (float*)d_out;

    cudaFuncSetAttribute(fkan_hmma, cudaFuncAttributeMaxDynamicSharedMemorySize, DYN_SMEM);
    fkan_conv<<<10240, 512>>>(fc);
    fkan_hmma<<<dim3(SPLITK, 8), 256, DYN_SMEM>>>(x);
    fkan_reduce<<<128, 512>>>(bias, out);
}

// round 16
// speedup vs baseline: 1.1594x; 1.0765x over previous
#include <cuda_runtime.h>
#include <cstdint>
#include <math.h>

// NaiveFourierKANLayer, fp16 mma.sync single term, R16:
//  - conv kernel ELIMINATED: B (coeffs*2048 -> fp16) converted in-kernel,
//    LDG+pack+STS interleaved under the MMA run (one 128B line per thread/stage)
//  - CTA tile 256M x 128N (grid 18x4x2 = 144 CTAs), 8 warps, 64x64 warp tiles
//  - uneven split-K 18 over i; fp32 scratch + float4 reduce

#define NI 256
#define NG 300
#define NO 256
#define SPLITK 18
#define NGC 10               // 32-g chunks per i (chunk 9 zero-padded)

#define RSB 144              // smem row pitch -> conflict-free ldmatrix
#define A_OFF 0              // 256 rows
#define B_OFF 36864          // 128 rows
#define STAGE_BYTES 55296
#define DYN_SMEM (2*STAGE_BYTES)

#define BSCALE 2048.0f
#define FSCALE (1.0f/2048.0f)

__device__ float g_scratch[SPLITK * 1024 * 256];   // 18.9 MB split-K partials

// ---------------- helpers ----------------
__device__ __forceinline__ uint32_t smem_u32(const void* p) {
    uint32_t a;
    asm("{ .reg .u64 t; cvta.to.shared.u64 t, %1; cvt.u32.u64 %0, t; }" : "=r"(a) : "l"(p));
    return a;
}
__device__ __forceinline__ uint32_t packf16(float a, float b) {
    uint32_t r;
    asm("cvt.rn.f16x2.f32 %0, %2, %1;" : "=r"(r) : "f"(a), "f"(b));
    return r;
}
__device__ __forceinline__ void rotstep(float& c, float& s, float cr, float sr) {
    float nc = fmaf(c, cr, -(s * sr));
    float ns = fmaf(s, cr, c * sr);
    c = nc; s = ns;
}

#define LDSM4(r0,r1,r2,r3,addr)                                                  \
    asm volatile("ldmatrix.sync.aligned.m8n8.x4.shared.b16 {%0,%1,%2,%3}, [%4];" \
        : "=r"(r0), "=r"(r1), "=r"(r2), "=r"(r3) : "r"(addr))

#define MMA(d,a,b0,b1)                                                        \
    asm volatile("mma.sync.aligned.m16n8k16.row.col.f32.f16.f16.f32 "         \
        "{%0,%1,%2,%3},{%4,%5,%6,%7},{%8,%9},{%0,%1,%2,%3};"                  \
        : "+f"((d)[0]), "+f"((d)[1]), "+f"((d)[2]), "+f"((d)[3])              \
        : "r"((a)[0]), "r"((a)[1]), "r"((a)[2]), "r"((a)[3]), "r"(b0), "r"(b1))

extern __shared__ char dsmem[];

// ---------------- main MMA kernel (fused B conversion) ----------------
__global__ void __launch_bounds__(256, 1)
fkan_hmma(const float* __restrict__ x, const float* __restrict__ fc)
{
    const int tid  = threadIdx.x;
    const int lane = tid & 31;
    const int w    = tid >> 5;
    const int ks = blockIdx.x;                 // 0..17 uneven split-K over i
    const int m0 = blockIdx.y * 256;           // 4 m-tiles
    const int n0 = blockIdx.z * 128;           // 2 n-tiles

    // slice boundaries: first 4 slices take 15 i, rest 14 (4*15+14*14=256)
    const int i0  = ks * 14 + min(ks, 4);
    const int ipc = 14 + (ks < 4 ? 1 : 0);
    const int nst = ipc * NGC;

    const uint32_t smb = smem_u32(dsmem);

    // ---- producer maps ----
    const int rr = tid;                        // A: one row per thread (0..255)
    const int bt = tid >> 7, bj = tid & 127;   // B: trig part, j-row
    const float* bbase = fc + ((size_t)(bt * NO + n0 + bj) * NI + i0) * NG;

    // ---- mma maps: 8 warps = 4(M) x 2(N), warp tile 64x64 ----
    const int wm = w & 3, wn = w >> 2;
    const uint32_t aoff = (uint32_t)(wm*64 + (lane & 7) + ((lane >> 3) & 1)*8) * RSB
                        + (uint32_t)(lane >> 4) * 16;
    const uint32_t boff = (uint32_t)(wn*64 + (lane & 7) + (lane >> 4)*8) * RSB
                        + (uint32_t)((lane >> 3) & 1) * 16;

    float acc[4][8][4];
    #pragma unroll
    for (int a = 0; a < 4; ++a)
        #pragma unroll
        for (int b = 0; b < 8; ++b)
            #pragma unroll
            for (int c = 0; c < 4; ++c) acc[a][b][c] = 0.f;

    const float* xcol = x + (size_t)(m0 + rr) * NI + i0;

    // rotation state (for NEXT stage to be produced); only 1t and 2t steps needed
    float c1, s1, c2, s2, cc, ss;
    int png = 0, pni = 0;

    #define SETUP_I(ii) do {                                                   \
        const float t_ = xcol[ii];                                             \
        sincosf(t_, &s1, &c1);                                                 \
        c2 = fmaf(c1, c1, -(s1*s1)); s2 = 2.f*c1*s1;                           \
        cc = c1; ss = s1;                                                      \
    } while (0)

    // produce adjacent pair m (g = png*32 + 2m, 2m+1): cos k=2m, sin k=32+2m
    #define GEN_PAIR(smn, m) do {                                              \
        const int gl_ = 2*(m);                                                 \
        const int gg_ = png*32 + gl_;                                          \
        float ce_ = cc, se_ = ss;                                              \
        float co_ = fmaf(cc, c1, -(ss*s1));                                    \
        float so_ = fmaf(ss, c1,  cc*s1);                                      \
        if (gg_     >= NG) { ce_ = 0.f; se_ = 0.f; }                           \
        if (gg_ + 1 >= NG) { co_ = 0.f; so_ = 0.f; }                           \
        const uint32_t offc_ = (uint32_t)rr * RSB + (uint32_t)gl_ * 2;         \
        *(uint32_t*)((smn) + A_OFF + offc_)      = packf16(ce_, co_);          \
        *(uint32_t*)((smn) + A_OFF + offc_ + 64) = packf16(se_, so_);          \
        rotstep(cc, ss, c2, s2);                                               \
    } while (0)

    #define ADV_CHUNK() do { if (++png == NGC) { png = 0; ++pni; } } while (0)

    // B: load 32 fp32 of chunk (pni, png) into bf (guards for g >= NG)
    #define BLOAD(bf) do {                                                     \
        const float* p_ = bbase + (size_t)pni * NG + png * 32;                 \
        _Pragma("unroll")                                                      \
        for (int q4 = 0; q4 < 8; ++q4) {                                       \
            const int g0_ = png*32 + q4*4;                                     \
            (bf)[q4] = (g0_ + 3 < NG) ? *(const float4*)(p_ + q4*4)            \
                                      : make_float4(0.f, 0.f, 0.f, 0.f);       \
        }                                                                      \
    } while (0)

    #define BSTS(smn, bf) do {                                                 \
        const float* bv_ = (const float*)(bf);                                 \
        _Pragma("unroll")                                                      \
        for (int pp = 0; pp < 16; ++pp) {                                      \
            const uint32_t hp_ = packf16(bv_[2*pp] * BSCALE, bv_[2*pp+1] * BSCALE); \
            const uint32_t off_ = (uint32_t)bj * RSB + (uint32_t)(bt*32 + 2*pp) * 2; \
            *(uint32_t*)((smn) + B_OFF + off_) = hp_;                          \
        }                                                                      \
    } while (0)

    #define CONSUME_KK(kk) do {                                                \
        uint32_t bh[16];                                                       \
        _Pragma("unroll")                                                      \
        for (int p = 0; p < 4; ++p)                                            \
            LDSM4(bh[4*p], bh[4*p+1], bh[4*p+2], bh[4*p+3],                    \
                  pB + p*(16*RSB) + (kk)*32);                                  \
        uint32_t ah[4][4];                                                     \
        _Pragma("unroll")                                                      \
        for (int mf = 0; mf < 4; ++mf)                                         \
            LDSM4(ah[mf][0], ah[mf][1], ah[mf][2], ah[mf][3],                  \
                  pA + mf*(16*RSB) + (kk)*32);                                 \
        _Pragma("unroll")                                                      \
        for (int mf = 0; mf < 4; ++mf)                                         \
            _Pragma("unroll")                                                  \
            for (int f = 0; f < 8; ++f)                                        \
                MMA(acc[mf][f], ah[mf], bh[2*f], bh[2*f+1]);                   \
    } while (0)

    // ---- prologue: produce stage 0 (A + B) into buffer 0 ----
    SETUP_I(0);
    {
        char* sm0 = dsmem;
        float4 bf[8];
        BLOAD(bf);
        #pragma unroll
        for (int m = 0; m < 16; ++m) GEN_PAIR(sm0, m);
        BSTS(sm0, bf);
        ADV_CHUNK();
    }

    int cgc = 0;
    for (int it = 0; it < nst; ++it) {
        __syncthreads();                    // stage it fully visible

        const bool dp = (it + 1 < nst);
        char* smn = dsmem + ((it + 1) & 1) * STAGE_BYTES;

        // load B fp32 for stage it+1 (latency covered by 2 kk blocks ~2000cyc)
        float4 bf[8];
        if (dp) BLOAD(bf);

        const uint32_t stg = (uint32_t)(it & 1) * STAGE_BYTES;
        const uint32_t pA = smb + stg + aoff;
        const uint32_t pB = smb + stg + B_OFF + boff;

        if (cgc != 9) {
            CONSUME_KK(0);
            if (dp) { if (png == 0) SETUP_I(pni);
                      GEN_PAIR(smn, 0); GEN_PAIR(smn, 1);
                      GEN_PAIR(smn, 2); GEN_PAIR(smn, 3); }
            CONSUME_KK(1);
            if (dp) { GEN_PAIR(smn, 4); GEN_PAIR(smn, 5);
                      GEN_PAIR(smn, 6); GEN_PAIR(smn, 7); }
            CONSUME_KK(2);
            if (dp) { BSTS(smn, bf);
                      GEN_PAIR(smn, 8); GEN_PAIR(smn, 9);
                      GEN_PAIR(smn, 10); GEN_PAIR(smn, 11); }
            CONSUME_KK(3);
            if (dp) { GEN_PAIR(smn, 12); GEN_PAIR(smn, 13);
                      GEN_PAIR(smn, 14); GEN_PAIR(smn, 15); ADV_CHUNK(); }
        } else {
            // padded chunk: only kk=0 and kk=2 carry data
            CONSUME_KK(0);
            if (dp) { if (png == 0) SETUP_I(pni);
                      GEN_PAIR(smn, 0); GEN_PAIR(smn, 1);
                      GEN_PAIR(smn, 2); GEN_PAIR(smn, 3);
                      GEN_PAIR(smn, 4); GEN_PAIR(smn, 5);
                      GEN_PAIR(smn, 6); GEN_PAIR(smn, 7); }
            CONSUME_KK(2);
            if (dp) { BSTS(smn, bf);
                      GEN_PAIR(smn, 8); GEN_PAIR(smn, 9);
                      GEN_PAIR(smn, 10); GEN_PAIR(smn, 11);
                      GEN_PAIR(smn, 12); GEN_PAIR(smn, 13);
                      GEN_PAIR(smn, 14); GEN_PAIR(smn, 15); ADV_CHUNK(); }
        }
        if (++cgc == NGC) cgc = 0;
    }

    // ---- epilogue: accumulators (x2048) -> split-K scratch ----
    float* dst = g_scratch + ((size_t)ks << 18);
    #pragma unroll
    for (int mf = 0; mf < 4; ++mf) {
        const int r = m0 + wm*64 + mf*16 + (lane >> 2);
        #pragma unroll
        for (int f = 0; f < 8; ++f) {
            const int c = n0 + wn*64 + f*8 + (lane & 3)*2;
            float2 v0, v1;
            v0.x = acc[mf][f][0] * FSCALE; v0.y = acc[mf][f][1] * FSCALE;
            v1.x = acc[mf][f][2] * FSCALE; v1.y = acc[mf][f][3] * FSCALE;
            *(float2*)(dst + (size_t)r * NO + c)       = v0;
            *(float2*)(dst + (size_t)(r + 8) * NO + c) = v1;
        }
    }
}

// ---------------- split-K reduce (float4 per thread) ----------------
__global__ void __launch_bounds__(512, 1)
fkan_reduce(const float* __restrict__ bias, float* __restrict__ out)
{
    const int base = (blockIdx.x * 512 + threadIdx.x) * 4;   // 128 blocks -> 262144
    float4 a = *(const float4*)(bias + (base & 255));
    #pragma unroll
    for (int k = 0; k < SPLITK; ++k) {
        const float4 v = *(const float4*)(g_scratch + ((size_t)k << 18) + base);
        a.x += v.x; a.y += v.y; a.z += v.z; a.w += v.w;
    }
    *(float4*)(out + base) = a;
}

extern "C" void kernel_launch(void* const* d_in, const int* in_sizes, int n_in,
                              void* d_out, int out_size) {
    const float* x    = (const float*)d_in[0];
    const float* fc   = (const float*)d_in[1];
    const float* bias = (const float*)d_in[2];
    float* out        = (float*)d_out;

    cudaFuncSetAttribute(fkan_hmma, cudaFuncAttributeMaxDynamicSharedMemorySize, DYN_SMEM);
    fkan_hmma<<<dim3(SPLITK, 4, 2), 256, DYN_SMEM>>>(x, fc);
    fkan_reduce<<<128, 512>>>(bias, out);
}

// round 17
// speedup vs baseline: 1.2078x; 1.0418x over previous
#include <cuda_runtime.h>
#include <cstdint>
#include <math.h>

// NaiveFourierKANLayer, fp16 mma.sync single term, R17:
//  - chunk-level split-K: 2560 (i,gc) chunks over 18 slices (143/142) ->
//    critical path 143 stages (was 150 with whole-i slices)
//  - fused in-kernel B conversion (R16), CTA tile 256M x 128N, 64x64 warp tiles
//  - fp32 scratch + float4 reduce (256 blocks)

#define NI 256
#define NG 300
#define NO 256
#define SPLITK 18
#define NGC 10               // 32-g chunks per i (chunk 9 zero-padded)
#define NCHTOT (NI*NGC)      // 2560 chunks

#define RSB 144
#define A_OFF 0              // 256 rows
#define B_OFF 36864          // 128 rows
#define STAGE_BYTES 55296
#define DYN_SMEM (2*STAGE_BYTES)

#define BSCALE 2048.0f
#define FSCALE (1.0f/2048.0f)

__device__ float g_scratch[SPLITK * 1024 * 256];   // 18.9 MB split-K partials

// ---------------- helpers ----------------
__device__ __forceinline__ uint32_t smem_u32(const void* p) {
    uint32_t a;
    asm("{ .reg .u64 t; cvta.to.shared.u64 t, %1; cvt.u32.u64 %0, t; }" : "=r"(a) : "l"(p));
    return a;
}
__device__ __forceinline__ uint32_t packf16(float a, float b) {
    uint32_t r;
    asm("cvt.rn.f16x2.f32 %0, %2, %1;" : "=r"(r) : "f"(a), "f"(b));
    return r;
}
__device__ __forceinline__ void rotstep(float& c, float& s, float cr, float sr) {
    float nc = fmaf(c, cr, -(s * sr));
    float ns = fmaf(s, cr, c * sr);
    c = nc; s = ns;
}

#define LDSM4(r0,r1,r2,r3,addr)                                                  \
    asm volatile("ldmatrix.sync.aligned.m8n8.x4.shared.b16 {%0,%1,%2,%3}, [%4];" \
        : "=r"(r0), "=r"(r1), "=r"(r2), "=r"(r3) : "r"(addr))

#define MMA(d,a,b0,b1)                                                        \
    asm volatile("mma.sync.aligned.m16n8k16.row.col.f32.f16.f16.f32 "         \
        "{%0,%1,%2,%3},{%4,%5,%6,%7},{%8,%9},{%0,%1,%2,%3};"                  \
        : "+f"((d)[0]), "+f"((d)[1]), "+f"((d)[2]), "+f"((d)[3])              \
        : "r"((a)[0]), "r"((a)[1]), "r"((a)[2]), "r"((a)[3]), "r"(b0), "r"(b1))

extern __shared__ char dsmem[];

// ---------------- main MMA kernel (fused B conversion, chunk split-K) -----------
__global__ void __launch_bounds__(256, 1)
fkan_hmma(const float* __restrict__ x, const float* __restrict__ fc)
{
    const int tid  = threadIdx.x;
    const int lane = tid & 31;
    const int w    = tid >> 5;
    const int ks = blockIdx.x;                 // 0..17 chunk-level split-K
    const int m0 = blockIdx.y * 256;           // 4 m-tiles
    const int n0 = blockIdx.z * 128;           // 2 n-tiles

    // slice = chunk range [ch0, ch0+nst); 4 slices of 143, 14 of 142
    const int ch0 = ks * 142 + min(ks, 4);
    const int nst = 142 + (ks < 4 ? 1 : 0);

    const uint32_t smb = smem_u32(dsmem);

    // ---- producer maps ----
    const int rr = tid;                        // A: one row per thread
    const int bt = tid >> 7, bj = tid & 127;   // B: trig part, j-row
    const float* bbase = fc + ((size_t)(bt * NO + n0 + bj) * NI) * NG;

    // ---- mma maps: 8 warps = 4(M) x 2(N), warp tile 64x64 ----
    const int wm = w & 3, wn = w >> 2;
    const uint32_t aoff = (uint32_t)(wm*64 + (lane & 7) + ((lane >> 3) & 1)*8) * RSB
                        + (uint32_t)(lane >> 4) * 16;
    const uint32_t boff = (uint32_t)(wn*64 + (lane & 7) + (lane >> 4)*8) * RSB
                        + (uint32_t)((lane >> 3) & 1) * 16;

    float acc[4][8][4];
    #pragma unroll
    for (int a = 0; a < 4; ++a)
        #pragma unroll
        for (int b = 0; b < 8; ++b)
            #pragma unroll
            for (int c = 0; c < 4; ++c) acc[a][b][c] = 0.f;

    const float* xrow = x + (size_t)(m0 + rr) * NI;

    // rotation / production state (for NEXT chunk to produce)
    float c1, s1, c2, s2, cc, ss;
    int png = ch0 % NGC, pni = ch0 / NGC;

    #define SETUP_I(ii) do {                                                   \
        const float t_ = xrow[ii];                                             \
        sincosf(t_, &s1, &c1);                                                 \
        c2 = fmaf(c1, c1, -(s1*s1)); s2 = 2.f*c1*s1;                           \
        cc = c1; ss = s1;                                                      \
    } while (0)

    #define GEN_PAIR(smn, m) do {                                              \
        const int gl_ = 2*(m);                                                 \
        const int gg_ = png*32 + gl_;                                          \
        float ce_ = cc, se_ = ss;                                              \
        float co_ = fmaf(cc, c1, -(ss*s1));                                    \
        float so_ = fmaf(ss, c1,  cc*s1);                                      \
        if (gg_     >= NG) { ce_ = 0.f; se_ = 0.f; }                           \
        if (gg_ + 1 >= NG) { co_ = 0.f; so_ = 0.f; }                           \
        const uint32_t offc_ = (uint32_t)rr * RSB + (uint32_t)gl_ * 2;         \
        *(uint32_t*)((smn) + A_OFF + offc_)      = packf16(ce_, co_);          \
        *(uint32_t*)((smn) + A_OFF + offc_ + 64) = packf16(se_, so_);          \
        rotstep(cc, ss, c2, s2);                                               \
    } while (0)

    #define ADV_CHUNK() do { if (++png == NGC) { png = 0; ++pni; } } while (0)

    #define BLOAD(bf) do {                                                     \
        const float* p_ = bbase + (size_t)pni * NG + png * 32;                 \
        _Pragma("unroll")                                                      \
        for (int q4 = 0; q4 < 8; ++q4) {                                       \
            const int g0_ = png*32 + q4*4;                                     \
            (bf)[q4] = (g0_ + 3 < NG) ? *(const float4*)(p_ + q4*4)            \
                                      : make_float4(0.f, 0.f, 0.f, 0.f);       \
        }                                                                      \
    } while (0)

    #define BSTS(smn, bf) do {                                                 \
        const float* bv_ = (const float*)(bf);                                 \
        _Pragma("unroll")                                                      \
        for (int pp = 0; pp < 16; ++pp) {                                      \
            const uint32_t hp_ = packf16(bv_[2*pp] * BSCALE, bv_[2*pp+1] * BSCALE); \
            const uint32_t off_ = (uint32_t)bj * RSB + (uint32_t)(bt*32 + 2*pp) * 2; \
            *(uint32_t*)((smn) + B_OFF + off_) = hp_;                          \
        }                                                                      \
    } while (0)

    #define CONSUME_KK(kk) do {                                                \
        uint32_t bh[16];                                                       \
        _Pragma("unroll")                                                      \
        for (int p = 0; p < 4; ++p)                                            \
            LDSM4(bh[4*p], bh[4*p+1], bh[4*p+2], bh[4*p+3],                    \
                  pB + p*(16*RSB) + (kk)*32);                                  \
        uint32_t ah[4][4];                                                     \
        _Pragma("unroll")                                                      \
        for (int mf = 0; mf < 4; ++mf)                                         \
            LDSM4(ah[mf][0], ah[mf][1], ah[mf][2], ah[mf][3],                  \
                  pA + mf*(16*RSB) + (kk)*32);                                 \
        _Pragma("unroll")                                                      \
        for (int mf = 0; mf < 4; ++mf)                                         \
            _Pragma("unroll")                                                  \
            for (int f = 0; f < 8; ++f)                                        \
                MMA(acc[mf][f], ah[mf], bh[2*f], bh[2*f+1]);                   \
    } while (0)

    // ---- prologue: rotation state mid-i, then produce chunk ch0 ----
    SETUP_I(pni);
    if (png > 0) {
        // advance (cc,ss) from angle 1t to (png*32+1)t via 32t rotations
        const float c4_  = fmaf(c2,  c2,  -(s2 * s2)),   s4_  = 2.f * c2  * s2;
        const float c8_  = fmaf(c4_, c4_, -(s4_ * s4_)), s8_  = 2.f * c4_ * s4_;
        const float c16_ = fmaf(c8_, c8_, -(s8_ * s8_)), s16_ = 2.f * c8_ * s8_;
        const float c32_ = fmaf(c16_, c16_, -(s16_ * s16_)), s32_ = 2.f * c16_ * s16_;
        for (int a = 0; a < png; ++a) rotstep(cc, ss, c32_, s32_);
    }
    {
        char* sm0 = dsmem;
        float4 bf[8];
        BLOAD(bf);
        #pragma unroll
        for (int m = 0; m < 16; ++m) GEN_PAIR(sm0, m);
        BSTS(sm0, bf);
        ADV_CHUNK();
    }

    int cgc = ch0 % NGC;                       // gc of the stage being consumed
    for (int it = 0; it < nst; ++it) {
        __syncthreads();                       // stage it fully visible

        const bool dp = (it + 1 < nst);
        char* smn = dsmem + ((it + 1) & 1) * STAGE_BYTES;

        float4 bf[8];
        if (dp) BLOAD(bf);

        const uint32_t stg = (uint32_t)(it & 1) * STAGE_BYTES;
        const uint32_t pA = smb + stg + aoff;
        const uint32_t pB = smb + stg + B_OFF + boff;

        if (cgc != 9) {
            CONSUME_KK(0);
            if (dp) { if (png == 0) SETUP_I(pni);
                      GEN_PAIR(smn, 0); GEN_PAIR(smn, 1);
                      GEN_PAIR(smn, 2); GEN_PAIR(smn, 3); }
            CONSUME_KK(1);
            if (dp) { GEN_PAIR(smn, 4); GEN_PAIR(smn, 5);
                      GEN_PAIR(smn, 6); GEN_PAIR(smn, 7); }
            CONSUME_KK(2);
            if (dp) { BSTS(smn, bf);
                      GEN_PAIR(smn, 8); GEN_PAIR(smn, 9);
                      GEN_PAIR(smn, 10); GEN_PAIR(smn, 11); }
            CONSUME_KK(3);
            if (dp) { GEN_PAIR(smn, 12); GEN_PAIR(smn, 13);
                      GEN_PAIR(smn, 14); GEN_PAIR(smn, 15); ADV_CHUNK(); }
        } else {
            // padded chunk: only kk=0 and kk=2 carry data
            CONSUME_KK(0);
            if (dp) { if (png == 0) SETUP_I(pni);
                      GEN_PAIR(smn, 0); GEN_PAIR(smn, 1);
                      GEN_PAIR(smn, 2); GEN_PAIR(smn, 3);
                      GEN_PAIR(smn, 4); GEN_PAIR(smn, 5);
                      GEN_PAIR(smn, 6); GEN_PAIR(smn, 7); }
            CONSUME_KK(2);
            if (dp) { BSTS(smn, bf);
                      GEN_PAIR(smn, 8); GEN_PAIR(smn, 9);
                      GEN_PAIR(smn, 10); GEN_PAIR(smn, 11);
                      GEN_PAIR(smn, 12); GEN_PAIR(smn, 13);
                      GEN_PAIR(smn, 14); GEN_PAIR(smn, 15); ADV_CHUNK(); }
        }
        if (++cgc == NGC) cgc = 0;
    }

    // ---- epilogue: accumulators (x2048) -> split-K scratch ----
    float* dst = g_scratch + ((size_t)ks << 18);
    #pragma unroll
    for (int mf = 0; mf < 4; ++mf) {
        const int r = m0 + wm*64 + mf*16 + (lane >> 2);
        #pragma unroll
        for (int f = 0; f < 8; ++f) {
            const int c = n0 + wn*64 + f*8 + (lane & 3)*2;
            float2 v0, v1;
            v0.x = acc[mf][f][0] * FSCALE; v0.y = acc[mf][f][1] * FSCALE;
            v1.x = acc[mf][f][2] * FSCALE; v1.y = acc[mf][f][3] * FSCALE;
            *(float2*)(dst + (size_t)r * NO + c)       = v0;
            *(float2*)(dst + (size_t)(r + 8) * NO + c) = v1;
        }
    }
}

// ---------------- split-K reduce (float4 per thread, 256 blocks) ----------------
__global__ void __launch_bounds__(256, 1)
fkan_reduce(const float* __restrict__ bias, float* __restrict__ out)
{
    const int base = (blockIdx.x * 256 + threadIdx.x) * 4;   // 256 blocks -> 262144
    float4 a = *(const float4*)(bias + (base & 255));
    #pragma unroll
    for (int k = 0; k < SPLITK; ++k) {
        const float4 v = *(const float4*)(g_scratch + ((size_t)k << 18) + base);
        a.x += v.x; a.y += v.y; a.z += v.z; a.w += v.w;
    }
    *(float4*)(out + base) = a;
}

extern "C" void kernel_launch(void* const* d_in, const int* in_sizes, int n_in,
                              void* d_out, int out_size) {
    const float* x    = (const float*)d_in[0];
    const float* fc   = (const float*)d_in[1];
    const float* bias = (const float*)d_in[2];
    float* out        = (float*)d_out;

    cudaFuncSetAttribute(fkan_hmma, cudaFuncAttributeMaxDynamicSharedMemorySize, DYN_SMEM);
    fkan_hmma<<<dim3(SPLITK, 4, 2), 256, DYN_SMEM>>>(x, fc);
    fkan_reduce<<<256, 256>>>(bias, out);
}